// round 9
// baseline (speedup 1.0000x reference)
#include <cuda_runtime.h>

// KAN_Convolutional_Layer: B=8, CIN=4, H=W=64, OUT=8, K2=9, G=8, Ho=Wo=62
// R9 = R6's traffic economics at 4x the warps/scheduler:
//   tile 32x8 (256 px, best weight amortization), 1024 threads/block,
//   thread = 4-px strip x 8 outputs x 2 planes (16-way cg split).
//   128 blocks, 1 block/SM -> 8 warps/SMSP. R6's empirical strides kept.
//   16-plane staging over c-pairs; R8's proven 4-level butterfly reduction.

#define B_    8
#define CIN_  4
#define H_    64
#define W_    64
#define OUT_  8
#define K2_   9
#define G_    8
#define HO_   62
#define WO_   62
#define R2_   39.0625f     // R^2 folded into weights

#define TILW  36           // 32 px + 2 halo + 2 pad (float4 alignment)
#define TILH  10           // 8 rows + 2 halo
#define NPOS  (TILH*TILW)  // 360
#define PSTR  368          // R6 empirical plane stride
#define WCG   144          // R6 empirical dup'd-weight stride (9*16)
#define NTHR  1024

typedef unsigned long long u64;

__device__ __forceinline__ u64 pack2(float lo, float hi) {
    u64 r;
    asm("mov.b64 %0, {%1, %2};" : "=l"(r) : "f"(lo), "f"(hi));
    return r;
}
__device__ __forceinline__ void unpack2(u64 v, float& lo, float& hi) {
    asm("mov.b64 {%0, %1}, %2;" : "=f"(lo), "=f"(hi) : "l"(v));
}
__device__ __forceinline__ u64 fma2(u64 a, u64 b, u64 c) {
    u64 d;
    asm("fma.rn.f32x2 %0, %1, %2, %3;" : "=l"(d) : "l"(a), "l"(b), "l"(c));
    return d;
}
__device__ __forceinline__ u64 add2(u64 a, u64 b) {
    u64 d;
    asm("add.rn.f32x2 %0, %1, %2;" : "=l"(d) : "l"(a), "l"(b));
    return d;
}

__global__ void __launch_bounds__(NTHR, 1)
kan_fused_kernel(const float* __restrict__ x,
                 const float* __restrict__ phase_low,
                 const float* __restrict__ phase_high,
                 const float* __restrict__ weight,
                 const float* __restrict__ bias,
                 float* __restrict__ out) {
    __shared__ __align__(16) float tsh[16 * PSTR];   // 23.5 KB (one c-pair stage)
    __shared__ __align__(16) float wsh[32 * WCG];    // 18.4 KB, dup'd weights
    __shared__ float bsh[OUT_];

    const int b   = blockIdx.z;
    const int x0  = blockIdx.x * 32;
    const int y0  = blockIdx.y * 8;
    const int tid = threadIdx.x;

    // ---- duplicated weights: wsh[cg*WCG + f*16 + o*2 + {0,1}] = w*R^2
#pragma unroll
    for (int it = 0; it < 3; it++) {
        int i = tid + it * NTHR;
        if (i < 32 * K2_ * OUT_) {
            int o  = i & 7;
            int f  = (i >> 3) % K2_;
            int cg = i / (K2_ * OUT_);
            int g  = cg & 7;
            int c  = cg >> 3;
            float wv = weight[((o * CIN_ + c) * K2_ + f) * G_ + g] * R2_;
            int base = cg * WCG + f * 16 + o * 2;
            wsh[base]     = wv;
            wsh[base + 1] = wv;
        }
    }
    if (tid < OUT_) {
        float s = 0.0f;
#pragma unroll
        for (int c = 0; c < CIN_; c++) s += bias[tid * CIN_ + c];
        bsh[tid] = s;
    }

    float pl[G_], ph[G_];
#pragma unroll
    for (int g = 0; g < G_; g++) {
        pl[g] = __ldg(&phase_low[g]);   // broadcast over (o,c,f) by construction
        ph[g] = __ldg(&phase_high[g]);
    }

    // ---- lane decomposition
    const int w     = tid >> 5;          // warp 0..31
    const int l     = tid & 31;
    const int q     = l >> 1;            // cg group 0..15 (one plane per stage)
    const int sub   = l & 1;
    const int strip = w * 2 + sub;       // 0..63
    const int sy    = strip >> 3;        // row 0..7
    const int sxs   = strip & 7;         // strip col 0..7 -> px 4*sxs..4*sxs+3

    u64 acc[16];                         // [o*2 + pair]
#pragma unroll
    for (int k = 0; k < 16; k++) acc[k] = 0;

#pragma unroll
    for (int s = 0; s < 2; s++) {        // c-pair stages {0,1}, {2,3}
        __syncthreads();                 // prior stage reads done
        // -- spline fill: 2 c-planes x 8 g, 360 positions each (720 < 1024)
        if (tid < 2 * NPOS) {
            int cl  = tid >= NPOS;
            int pos = tid - cl * NPOS;
            int row = pos / TILW;
            int col = pos - row * TILW;
            int gy = y0 + row, gx = x0 + col;
            float xv = 0.0f;
            if (gy < H_ && gx < W_)
                xv = __ldg(&x[((b * CIN_ + 2 * s + cl) * H_ + gy) * W_ + gx]);
#pragma unroll
            for (int g = 0; g < G_; g++) {
                float a = fmaxf(xv - pl[g], 0.0f);
                float d = fmaxf(ph[g] - xv, 0.0f);
                float m = a * d;
                tsh[(cl * G_ + g) * PSTR + pos] = m * m;   // R^2 in weights
            }
        }
        __syncthreads();

        // -- conv: this thread handles plane q of the stage
        const float* pb = tsh + q * PSTR + sy * TILW + 4 * sxs;  // 16B aligned
        const float* wp = wsh + (s * 16 + q) * WCG;

#pragma unroll
        for (int fi = 0; fi < 3; fi++) {
            // row-streamed tv: 6 values -> 5 px-pairs
            float4 v4 = *reinterpret_cast<const float4*>(pb + fi * TILW);
            float2 v2 = *reinterpret_cast<const float2*>(pb + fi * TILW + 4);
            u64 p01 = pack2(v4.x, v4.y);
            u64 p12 = pack2(v4.y, v4.z);
            u64 p23 = pack2(v4.z, v4.w);
            u64 p34 = pack2(v4.w, v2.x);
            u64 p45 = pack2(v2.x, v2.y);
            u64 pA[3] = {p01, p12, p23};   // (px0,px1) per fj
            u64 pB[3] = {p23, p34, p45};   // (px2,px3) per fj

#pragma unroll
            for (int fj = 0; fj < 3; fj++) {
                const ulonglong2* wv =
                    reinterpret_cast<const ulonglong2*>(wp + (fi * 3 + fj) * 16);
                ulonglong2 w01 = wv[0];   // dup'd o0, o1
                ulonglong2 w23 = wv[1];
                ulonglong2 w45 = wv[2];
                ulonglong2 w67 = wv[3];
                u64 ta = pA[fj];
                u64 tb = pB[fj];
                acc[0]  = fma2(ta, w01.x, acc[0]);
                acc[1]  = fma2(tb, w01.x, acc[1]);
                acc[2]  = fma2(ta, w01.y, acc[2]);
                acc[3]  = fma2(tb, w01.y, acc[3]);
                acc[4]  = fma2(ta, w23.x, acc[4]);
                acc[5]  = fma2(tb, w23.x, acc[5]);
                acc[6]  = fma2(ta, w23.y, acc[6]);
                acc[7]  = fma2(tb, w23.y, acc[7]);
                acc[8]  = fma2(ta, w45.x, acc[8]);
                acc[9]  = fma2(tb, w45.x, acc[9]);
                acc[10] = fma2(ta, w45.y, acc[10]);
                acc[11] = fma2(tb, w45.y, acc[11]);
                acc[12] = fma2(ta, w67.x, acc[12]);
                acc[13] = fma2(tb, w67.x, acc[13]);
                acc[14] = fma2(ta, w67.y, acc[14]);
                acc[15] = fma2(tb, w67.y, acc[15]);
            }
        }
    }

    // ---- 4-level butterfly half-exchange over the 16 q-groups (R8-proven)
#pragma unroll
    for (int lvl = 0; lvl < 4; lvl++) {
        const int mask = 2 << lvl;
        const int half = 8 >> lvl;
        const bool bit = (q >> lvl) & 1;
#pragma unroll
        for (int j = 0; j < 8; j++) {
            if (j < half) {
                u64 lo = acc[j], hi = acc[half + j];
                u64 sent = bit ? lo : hi;
                u64 rec  = __shfl_xor_sync(0xffffffffu, sent, mask);
                acc[j] = add2(bit ? hi : lo, rec);
            }
        }
    }
    const int o    = ((q & 1) << 2) | (q & 2) | ((q >> 2) & 1);
    const int pair = (q >> 3) & 1;

    float v0, v1;
    unpack2(acc[0], v0, v1);
    const float bo = bsh[o];
    const int oy  = y0 + sy;
    const int ox0 = x0 + 4 * sxs + 2 * pair;
    if (oy < HO_) {
        float* op = out + ((b * OUT_ + o) * HO_ + oy) * WO_ + ox0;
        if (ox0 < WO_)     op[0] = v0 + bo;
        if (ox0 + 1 < WO_) op[1] = v1 + bo;
    }
}

// ---------------------------------------------------------------------------
extern "C" void kernel_launch(void* const* d_in, const int* in_sizes, int n_in,
                              void* d_out, int out_size) {
    const float* x          = (const float*)d_in[0];
    const float* phase_low  = (const float*)d_in[1];
    const float* phase_high = (const float*)d_in[2];
    const float* weight     = (const float*)d_in[3];
    const float* bias       = (const float*)d_in[4];
    float* out = (float*)d_out;

    dim3 grid(2, 8, B_);                 // 128 blocks x 1024 threads
    kan_fused_kernel<<<grid, NTHR>>>(x, phase_low, phase_high, weight, bias, out);
}

// round 10
// speedup vs baseline: 1.4521x; 1.4521x over previous
#include <cuda_runtime.h>

// KAN_Convolutional_Layer: B=8, CIN=4, H=W=64, OUT=8, K2=9, G=8, Ho=Wo=62
// R10: halve weight-LDS traffic per pixel vs R6.
//   128 blocks x 256 threads; tile 32x8; thread = 8-px strip x 8 outputs
//   x 4 of 32 (c,g) planes (8-way split, q = lane>>2 -- R6's 1-wavefront width).
//   R6's empirical strides (PSTR=368, WCG=144) kept verbatim.
//   32 f32x2 accumulators; weights loaded once per (plane,f), used 4x.
//   3-level butterfly: lane ends with one o x 8 px -> 4 aligned float2 stores.

#define B_    8
#define CIN_  4
#define H_    64
#define W_    64
#define OUT_  8
#define K2_   9
#define G_    8
#define HO_   62
#define WO_   62
#define R2_   39.0625f     // R^2 folded into weights

#define TILW  36           // 32 px + 2 halo + 2 pad (float4 alignment)
#define TILH  10
#define NPOS  (TILH*TILW)  // 360
#define PSTR  368          // R6 empirical plane stride
#define WCG   144          // R6 empirical dup'd-weight stride (9*16)
#define NTHR  256

typedef unsigned long long u64;

__device__ __forceinline__ u64 pack2(float lo, float hi) {
    u64 r;
    asm("mov.b64 %0, {%1, %2};" : "=l"(r) : "f"(lo), "f"(hi));
    return r;
}
__device__ __forceinline__ void unpack2(u64 v, float& lo, float& hi) {
    asm("mov.b64 {%0, %1}, %2;" : "=f"(lo), "=f"(hi) : "l"(v));
}
__device__ __forceinline__ u64 fma2(u64 a, u64 b, u64 c) {
    u64 d;
    asm("fma.rn.f32x2 %0, %1, %2, %3;" : "=l"(d) : "l"(a), "l"(b), "l"(c));
    return d;
}
__device__ __forceinline__ u64 add2(u64 a, u64 b) {
    u64 d;
    asm("add.rn.f32x2 %0, %1, %2;" : "=l"(d) : "l"(a), "l"(b));
    return d;
}

__global__ void __launch_bounds__(NTHR, 2)
kan_fused_kernel(const float* __restrict__ x,
                 const float* __restrict__ phase_low,
                 const float* __restrict__ phase_high,
                 const float* __restrict__ weight,
                 const float* __restrict__ bias,
                 float* __restrict__ out) {
    __shared__ __align__(16) float tsh[16 * PSTR];   // 23.5 KB (one c-pair stage)
    __shared__ __align__(16) float wsh[32 * WCG];    // 18.4 KB, dup'd weights
    __shared__ float bsh[OUT_];

    const int b   = blockIdx.z;
    const int x0  = blockIdx.x * 32;
    const int y0  = blockIdx.y * 8;
    const int tid = threadIdx.x;

    // ---- duplicated weights: wsh[cg*WCG + f*16 + o*2 + {0,1}] = w*R^2
#pragma unroll
    for (int it = 0; it < 9; it++) {
        int i = tid + it * NTHR;
        if (i < 32 * K2_ * OUT_) {
            int o  = i & 7;
            int f  = (i >> 3) % K2_;
            int cg = i / (K2_ * OUT_);
            int g  = cg & 7;
            int c  = cg >> 3;
            float wv = weight[((o * CIN_ + c) * K2_ + f) * G_ + g] * R2_;
            int base = cg * WCG + f * 16 + o * 2;
            wsh[base]     = wv;
            wsh[base + 1] = wv;
        }
    }
    if (tid < OUT_) {
        float s = 0.0f;
#pragma unroll
        for (int c = 0; c < CIN_; c++) s += bias[tid * CIN_ + c];
        bsh[tid] = s;
    }

    float pl[G_], ph[G_];
#pragma unroll
    for (int g = 0; g < G_; g++) {
        pl[g] = __ldg(&phase_low[g]);   // broadcast over (o,c,f) by construction
        ph[g] = __ldg(&phase_high[g]);
    }

    // ---- lane decomposition: warp w, lane l; q = cg group, sub = strip in warp
    const int w     = tid >> 5;          // warp 0..7
    const int l     = tid & 31;
    const int q     = l >> 2;            // 0..7 (cg group)
    const int sub   = l & 3;
    const int strip = w * 4 + sub;       // 0..31 (8-px strips)
    const int sy    = strip >> 2;        // row 0..7
    const int sxs   = strip & 3;         // strip col 0..3 -> px 8*sxs..8*sxs+7

    u64 acc[32];                         // [o*4 + px_pair]
#pragma unroll
    for (int k = 0; k < 32; k++) acc[k] = 0;

#pragma unroll
    for (int s = 0; s < 2; s++) {        // c-pair stages {0,1}, {2,3}
        __syncthreads();                 // prior stage reads done
        // -- spline fill: 2 c-planes x 8 g, 360 positions each (720 over 256 thr)
#pragma unroll
        for (int it = 0; it < 3; it++) {
            int i = tid + it * NTHR;
            if (i < 2 * NPOS) {
                int cl  = i >= NPOS;
                int pos = i - cl * NPOS;
                int row = pos / TILW;
                int col = pos - row * TILW;
                int gy = y0 + row, gx = x0 + col;
                float xv = 0.0f;
                if (gy < H_ && gx < W_)
                    xv = __ldg(&x[((b * CIN_ + 2 * s + cl) * H_ + gy) * W_ + gx]);
#pragma unroll
                for (int g = 0; g < G_; g++) {
                    float a = fmaxf(xv - pl[g], 0.0f);
                    float d = fmaxf(ph[g] - xv, 0.0f);
                    float m = a * d;
                    tsh[(cl * G_ + g) * PSTR + pos] = m * m;   // R^2 in weights
                }
            }
        }
        __syncthreads();

        // -- conv: q handles planes q and q+8 of this stage
#pragma unroll
        for (int i = 0; i < 2; i++) {
            const int p = q + 8 * i;
            const float* pb = tsh + p * PSTR + sy * TILW + 8 * sxs;  // 16B aligned
            const float* wp = wsh + (s * 16 + p) * WCG;

#pragma unroll
            for (int fi = 0; fi < 3; fi++) {
                // row-streamed tv: 10 values -> 9 px-pairs
                float4 va = *reinterpret_cast<const float4*>(pb + fi * TILW);
                float4 vb = *reinterpret_cast<const float4*>(pb + fi * TILW + 4);
                float2 vc = *reinterpret_cast<const float2*>(pb + fi * TILW + 8);
                u64 e0 = pack2(va.x, va.y);
                u64 e1 = pack2(va.z, va.w);
                u64 e2 = pack2(vb.x, vb.y);
                u64 e3 = pack2(vb.z, vb.w);
                u64 e4 = pack2(vc.x, vc.y);
                u64 o0 = pack2(va.y, va.z);
                u64 o1 = pack2(va.w, vb.x);
                u64 o2 = pack2(vb.y, vb.z);
                u64 o3 = pack2(vb.w, vc.x);
                u64 pj0[4] = {e0, e1, e2, e3};   // fj = 0
                u64 pj1[4] = {o0, o1, o2, o3};   // fj = 1
                u64 pj2[4] = {e1, e2, e3, e4};   // fj = 2

#pragma unroll
                for (int fj = 0; fj < 3; fj++) {
                    const u64* pj = (fj == 0) ? pj0 : (fj == 1) ? pj1 : pj2;
                    const ulonglong2* wv =
                        reinterpret_cast<const ulonglong2*>(wp + (fi * 3 + fj) * 16);
                    ulonglong2 w01 = wv[0];   // dup'd o0, o1
                    ulonglong2 w23 = wv[1];
                    ulonglong2 w45 = wv[2];
                    ulonglong2 w67 = wv[3];
                    u64 wd[8] = {w01.x, w01.y, w23.x, w23.y,
                                 w45.x, w45.y, w67.x, w67.y};
#pragma unroll
                    for (int o = 0; o < 8; o++) {
#pragma unroll
                        for (int k = 0; k < 4; k++)
                            acc[o * 4 + k] = fma2(pj[k], wd[o], acc[o * 4 + k]);
                    }
                }
            }
        }
    }

    // ---- 3-level butterfly half-exchange over the 8 q-groups
    // consumes o bits: o bit2 <-> q bit0, o bit1 <-> q bit1, o bit0 <-> q bit2
#pragma unroll
    for (int lvl = 0; lvl < 3; lvl++) {
        const int mask = 4 << lvl;
        const int half = 16 >> lvl;
        const bool bit = (q >> lvl) & 1;
#pragma unroll
        for (int j = 0; j < 16; j++) {
            if (j < half) {
                u64 lo = acc[j], hi = acc[half + j];
                u64 sent = bit ? lo : hi;
                u64 rec  = __shfl_xor_sync(0xffffffffu, sent, mask);
                acc[j] = add2(bit ? hi : lo, rec);
            }
        }
    }
    // lane q holds acc[0..3] = 4 px-pairs of output channel o = bitrev3(q)
    const int o = ((q & 1) << 2) | (q & 2) | ((q >> 2) & 1);

    const float bo = bsh[o];
    const int oy  = y0 + sy;
    const int ox0 = x0 + 8 * sxs;
    if (oy < HO_) {
        float* op = out + ((b * OUT_ + o) * HO_ + oy) * WO_;
#pragma unroll
        for (int k = 0; k < 4; k++) {
            int ox = ox0 + 2 * k;
            float v0, v1;
            unpack2(acc[k], v0, v1);
            if (ox + 1 < WO_) {
                *reinterpret_cast<float2*>(op + ox) = make_float2(v0 + bo, v1 + bo);
            } else if (ox < WO_) {
                op[ox] = v0 + bo;
            }
        }
    }
}

// ---------------------------------------------------------------------------
extern "C" void kernel_launch(void* const* d_in, const int* in_sizes, int n_in,
                              void* d_out, int out_size) {
    const float* x          = (const float*)d_in[0];
    const float* phase_low  = (const float*)d_in[1];
    const float* phase_high = (const float*)d_in[2];
    const float* weight     = (const float*)d_in[3];
    const float* bias       = (const float*)d_in[4];
    float* out = (float*)d_out;

    dim3 grid(2, 8, B_);                 // 128 blocks x 256 threads
    kan_fused_kernel<<<grid, NTHR>>>(x, phase_low, phase_high, weight, bias, out);
}

// round 11
// speedup vs baseline: 1.4812x; 1.0201x over previous
#include <cuda_runtime.h>

// KAN_Convolutional_Layer: B=8, CIN=4, H=W=64, OUT=8, K2=9, G=8, Ho=Wo=62
// R11 = R10 (best traffic economics: tile 32x8, 8-px strips, 8-way split,
// empirical strides) + scheduling freedom:
//   - __launch_bounds__(256,1): grid=128 < #SM, so 1 block/SM regardless;
//     give ptxas the full register file for hoisting (was capped at 128).
//   - batched weight loads: all 12 LDS.128 per (plane, fi) loaded before
//     the 96 fma2 block -> MLP=12, one LDS latency amortized per fi.

#define B_    8
#define CIN_  4
#define H_    64
#define W_    64
#define OUT_  8
#define K2_   9
#define G_    8
#define HO_   62
#define WO_   62
#define R2_   39.0625f     // R^2 folded into weights

#define TILW  36           // 32 px + 2 halo + 2 pad (float4 alignment)
#define TILH  10
#define NPOS  (TILH*TILW)  // 360
#define PSTR  368          // empirical best plane stride (R6/R10)
#define WCG   144          // empirical best dup'd-weight stride (9*16)
#define NTHR  256

typedef unsigned long long u64;

__device__ __forceinline__ u64 pack2(float lo, float hi) {
    u64 r;
    asm("mov.b64 %0, {%1, %2};" : "=l"(r) : "f"(lo), "f"(hi));
    return r;
}
__device__ __forceinline__ void unpack2(u64 v, float& lo, float& hi) {
    asm("mov.b64 {%0, %1}, %2;" : "=f"(lo), "=f"(hi) : "l"(v));
}
__device__ __forceinline__ u64 fma2(u64 a, u64 b, u64 c) {
    u64 d;
    asm("fma.rn.f32x2 %0, %1, %2, %3;" : "=l"(d) : "l"(a), "l"(b), "l"(c));
    return d;
}
__device__ __forceinline__ u64 add2(u64 a, u64 b) {
    u64 d;
    asm("add.rn.f32x2 %0, %1, %2;" : "=l"(d) : "l"(a), "l"(b));
    return d;
}

__global__ void __launch_bounds__(NTHR, 1)
kan_fused_kernel(const float* __restrict__ x,
                 const float* __restrict__ phase_low,
                 const float* __restrict__ phase_high,
                 const float* __restrict__ weight,
                 const float* __restrict__ bias,
                 float* __restrict__ out) {
    __shared__ __align__(16) float tsh[16 * PSTR];   // 23.5 KB (one c-pair stage)
    __shared__ __align__(16) float wsh[32 * WCG];    // 18.4 KB, dup'd weights
    __shared__ float bsh[OUT_];

    const int b   = blockIdx.z;
    const int x0  = blockIdx.x * 32;
    const int y0  = blockIdx.y * 8;
    const int tid = threadIdx.x;

    // ---- duplicated weights: wsh[cg*WCG + f*16 + o*2 + {0,1}] = w*R^2
#pragma unroll
    for (int it = 0; it < 9; it++) {
        int i = tid + it * NTHR;
        if (i < 32 * K2_ * OUT_) {
            int o  = i & 7;
            int f  = (i >> 3) % K2_;
            int cg = i / (K2_ * OUT_);
            int g  = cg & 7;
            int c  = cg >> 3;
            float wv = weight[((o * CIN_ + c) * K2_ + f) * G_ + g] * R2_;
            int base = cg * WCG + f * 16 + o * 2;
            wsh[base]     = wv;
            wsh[base + 1] = wv;
        }
    }
    if (tid < OUT_) {
        float s = 0.0f;
#pragma unroll
        for (int c = 0; c < CIN_; c++) s += bias[tid * CIN_ + c];
        bsh[tid] = s;
    }

    float pl[G_], ph[G_];
#pragma unroll
    for (int g = 0; g < G_; g++) {
        pl[g] = __ldg(&phase_low[g]);   // broadcast over (o,c,f) by construction
        ph[g] = __ldg(&phase_high[g]);
    }

    // ---- lane decomposition
    const int w     = tid >> 5;          // warp 0..7
    const int l     = tid & 31;
    const int q     = l >> 2;            // 0..7 (cg group)
    const int sub   = l & 3;
    const int strip = w * 4 + sub;       // 0..31 (8-px strips)
    const int sy    = strip >> 2;        // row 0..7
    const int sxs   = strip & 3;         // strip col 0..3 -> px 8*sxs..8*sxs+7

    u64 acc[32];                         // [o*4 + px_pair]
#pragma unroll
    for (int k = 0; k < 32; k++) acc[k] = 0;

#pragma unroll
    for (int s = 0; s < 2; s++) {        // c-pair stages {0,1}, {2,3}
        __syncthreads();                 // prior stage reads done
        // -- spline fill: 2 c-planes x 8 g, 360 positions each
#pragma unroll
        for (int it = 0; it < 3; it++) {
            int i = tid + it * NTHR;
            if (i < 2 * NPOS) {
                int cl  = i >= NPOS;
                int pos = i - cl * NPOS;
                int row = pos / TILW;
                int col = pos - row * TILW;
                int gy = y0 + row, gx = x0 + col;
                float xv = 0.0f;
                if (gy < H_ && gx < W_)
                    xv = __ldg(&x[((b * CIN_ + 2 * s + cl) * H_ + gy) * W_ + gx]);
#pragma unroll
                for (int g = 0; g < G_; g++) {
                    float a = fmaxf(xv - pl[g], 0.0f);
                    float d = fmaxf(ph[g] - xv, 0.0f);
                    float m = a * d;
                    tsh[(cl * G_ + g) * PSTR + pos] = m * m;   // R^2 in weights
                }
            }
        }
        __syncthreads();

        // -- conv: q handles planes q and q+8 of this stage
#pragma unroll
        for (int i = 0; i < 2; i++) {
            const int p = q + 8 * i;
            const float* pb = tsh + p * PSTR + sy * TILW + 8 * sxs;  // 16B aligned
            const float* wp = wsh + (s * 16 + p) * WCG;

#pragma unroll
            for (int fi = 0; fi < 3; fi++) {
                // -- batch ALL loads for this (plane, fi) first: 3 tv + 12 w
                float4 va = *reinterpret_cast<const float4*>(pb + fi * TILW);
                float4 vb = *reinterpret_cast<const float4*>(pb + fi * TILW + 4);
                float2 vc = *reinterpret_cast<const float2*>(pb + fi * TILW + 8);

                ulonglong2 wv[3][4];
#pragma unroll
                for (int fj = 0; fj < 3; fj++) {
                    const ulonglong2* wj =
                        reinterpret_cast<const ulonglong2*>(wp + (fi * 3 + fj) * 16);
                    wv[fj][0] = wj[0];
                    wv[fj][1] = wj[1];
                    wv[fj][2] = wj[2];
                    wv[fj][3] = wj[3];
                }

                // -- pack px pairs (10 tv values -> 9 pairs)
                u64 e0 = pack2(va.x, va.y);
                u64 e1 = pack2(va.z, va.w);
                u64 e2 = pack2(vb.x, vb.y);
                u64 e3 = pack2(vb.z, vb.w);
                u64 e4 = pack2(vc.x, vc.y);
                u64 o0 = pack2(va.y, va.z);
                u64 o1 = pack2(va.w, vb.x);
                u64 o2 = pack2(vb.y, vb.z);
                u64 o3 = pack2(vb.w, vc.x);
                u64 pj[3][4] = {{e0, e1, e2, e3},    // fj = 0
                                {o0, o1, o2, o3},    // fj = 1
                                {e1, e2, e3, e4}};   // fj = 2

                // -- 96 fma2, all operands in registers
#pragma unroll
                for (int fj = 0; fj < 3; fj++) {
                    u64 wd[8] = {wv[fj][0].x, wv[fj][0].y, wv[fj][1].x, wv[fj][1].y,
                                 wv[fj][2].x, wv[fj][2].y, wv[fj][3].x, wv[fj][3].y};
#pragma unroll
                    for (int o = 0; o < 8; o++) {
#pragma unroll
                        for (int k = 0; k < 4; k++)
                            acc[o * 4 + k] = fma2(pj[fj][k], wd[o], acc[o * 4 + k]);
                    }
                }
            }
        }
    }

    // ---- 3-level butterfly half-exchange over the 8 q-groups
#pragma unroll
    for (int lvl = 0; lvl < 3; lvl++) {
        const int mask = 4 << lvl;
        const int half = 16 >> lvl;
        const bool bit = (q >> lvl) & 1;
#pragma unroll
        for (int j = 0; j < 16; j++) {
            if (j < half) {
                u64 lo = acc[j], hi = acc[half + j];
                u64 sent = bit ? lo : hi;
                u64 rec  = __shfl_xor_sync(0xffffffffu, sent, mask);
                acc[j] = add2(bit ? hi : lo, rec);
            }
        }
    }
    // lane q holds acc[0..3] = 4 px-pairs of output channel o = bitrev3(q)
    const int o = ((q & 1) << 2) | (q & 2) | ((q >> 2) & 1);

    const float bo = bsh[o];
    const int oy  = y0 + sy;
    const int ox0 = x0 + 8 * sxs;
    if (oy < HO_) {
        float* op = out + ((b * OUT_ + o) * HO_ + oy) * WO_;
#pragma unroll
        for (int k = 0; k < 4; k++) {
            int ox = ox0 + 2 * k;
            float v0, v1;
            unpack2(acc[k], v0, v1);
            if (ox + 1 < WO_) {
                *reinterpret_cast<float2*>(op + ox) = make_float2(v0 + bo, v1 + bo);
            } else if (ox < WO_) {
                op[ox] = v0 + bo;
            }
        }
    }
}

// ---------------------------------------------------------------------------
extern "C" void kernel_launch(void* const* d_in, const int* in_sizes, int n_in,
                              void* d_out, int out_size) {
    const float* x          = (const float*)d_in[0];
    const float* phase_low  = (const float*)d_in[1];
    const float* phase_high = (const float*)d_in[2];
    const float* weight     = (const float*)d_in[3];
    const float* bias       = (const float*)d_in[4];
    float* out = (float*)d_out;

    dim3 grid(2, 8, B_);                 // 128 blocks x 256 threads, 1 block/SM
    kan_fused_kernel<<<grid, NTHR>>>(x, phase_low, phase_high, weight, bias, out);
}

// round 12
// speedup vs baseline: 1.7642x; 1.1910x over previous
#include <cuda_runtime.h>

// KAN_Convolutional_Layer: B=8, CIN=4, H=W=64, OUT=8, K2=9, G=8, Ho=Wo=62
// R12 = R10/R11 traffic economics + explicit latency pipelining:
//   - ALL x loads hoisted to kernel start (6 regs/thread): one DRAM-latency
//     exposure instead of two barrier-serialized ones.
//   - conv inner loop double-buffered in registers: load (plane,fi) iter j+1
//     while computing iter j -> LDS latency overlapped by compute.
//   Tile 32x8, 8-px strips, 8-way cg split, strides PSTR=368/WCG=144 kept.

#define B_    8
#define CIN_  4
#define H_    64
#define W_    64
#define OUT_  8
#define K2_   9
#define G_    8
#define HO_   62
#define WO_   62
#define R2_   39.0625f     // R^2 folded into weights

#define TILW  36           // 32 px + 2 halo + 2 pad (float4 alignment)
#define TILH  10
#define NPOS  (TILH*TILW)  // 360
#define PSTR  368          // empirical best plane stride
#define WCG   144          // empirical best dup'd-weight stride (9*16)
#define NTHR  256

typedef unsigned long long u64;

__device__ __forceinline__ u64 pack2(float lo, float hi) {
    u64 r;
    asm("mov.b64 %0, {%1, %2};" : "=l"(r) : "f"(lo), "f"(hi));
    return r;
}
__device__ __forceinline__ void unpack2(u64 v, float& lo, float& hi) {
    asm("mov.b64 {%0, %1}, %2;" : "=f"(lo), "=f"(hi) : "l"(v));
}
__device__ __forceinline__ u64 fma2(u64 a, u64 b, u64 c) {
    u64 d;
    asm("fma.rn.f32x2 %0, %1, %2, %3;" : "=l"(d) : "l"(a), "l"(b), "l"(c));
    return d;
}
__device__ __forceinline__ u64 add2(u64 a, u64 b) {
    u64 d;
    asm("add.rn.f32x2 %0, %1, %2;" : "=l"(d) : "l"(a), "l"(b));
    return d;
}

__global__ void __launch_bounds__(NTHR, 1)
kan_fused_kernel(const float* __restrict__ x,
                 const float* __restrict__ phase_low,
                 const float* __restrict__ phase_high,
                 const float* __restrict__ weight,
                 const float* __restrict__ bias,
                 float* __restrict__ out) {
    __shared__ __align__(16) float tsh[16 * PSTR];   // 23.5 KB (one c-pair stage)
    __shared__ __align__(16) float wsh[32 * WCG];    // 18.4 KB, dup'd weights
    __shared__ float bsh[OUT_];

    const int b   = blockIdx.z;
    const int x0  = blockIdx.x * 32;
    const int y0  = blockIdx.y * 8;
    const int tid = threadIdx.x;

    // ======== prologue: issue ALL global loads up front ========
    // x values for both spline stages: 6 per thread (4 c-planes x 360 pos)
    float xreg[6];
#pragma unroll
    for (int s = 0; s < 2; s++) {
#pragma unroll
        for (int it = 0; it < 3; it++) {
            int i = tid + it * NTHR;
            float xv = 0.0f;
            if (i < 2 * NPOS) {
                int cl  = i >= NPOS;
                int pos = i - cl * NPOS;
                int row = pos / TILW;
                int col = pos - row * TILW;
                int gy = y0 + row, gx = x0 + col;
                if (gy < H_ && gx < W_)
                    xv = __ldg(&x[((b * CIN_ + 2 * s + cl) * H_ + gy) * W_ + gx]);
            }
            xreg[s * 3 + it] = xv;
        }
    }

    // duplicated weights: wsh[cg*WCG + f*16 + o*2 + {0,1}] = w*R^2
#pragma unroll
    for (int it = 0; it < 9; it++) {
        int i = tid + it * NTHR;
        if (i < 32 * K2_ * OUT_) {
            int o  = i & 7;
            int f  = (i >> 3) % K2_;
            int cg = i / (K2_ * OUT_);
            int g  = cg & 7;
            int c  = cg >> 3;
            float wv = weight[((o * CIN_ + c) * K2_ + f) * G_ + g] * R2_;
            int base = cg * WCG + f * 16 + o * 2;
            wsh[base]     = wv;
            wsh[base + 1] = wv;
        }
    }
    if (tid < OUT_) {
        float s = 0.0f;
#pragma unroll
        for (int c = 0; c < CIN_; c++) s += bias[tid * CIN_ + c];
        bsh[tid] = s;
    }

    float pl[G_], ph[G_];
#pragma unroll
    for (int g = 0; g < G_; g++) {
        pl[g] = __ldg(&phase_low[g]);   // broadcast over (o,c,f) by construction
        ph[g] = __ldg(&phase_high[g]);
    }

    // ---- lane decomposition
    const int w     = tid >> 5;          // warp 0..7
    const int l     = tid & 31;
    const int q     = l >> 2;            // 0..7 (cg group)
    const int sub   = l & 3;
    const int strip = w * 4 + sub;       // 0..31 (8-px strips)
    const int sy    = strip >> 2;        // row 0..7
    const int sxs   = strip & 3;         // strip col 0..3 -> px 8*sxs..8*sxs+7

    u64 acc[32];                         // [o*4 + px_pair]
#pragma unroll
    for (int k = 0; k < 32; k++) acc[k] = 0;

#pragma unroll
    for (int s = 0; s < 2; s++) {        // c-pair stages {0,1}, {2,3}
        if (s) __syncthreads();          // conv of prior stage done reading tsh
        // -- spline fill from registers (no DRAM wait here)
#pragma unroll
        for (int it = 0; it < 3; it++) {
            int i = tid + it * NTHR;
            if (i < 2 * NPOS) {
                int cl  = i >= NPOS;
                int pos = i - cl * NPOS;
                float xv = xreg[s * 3 + it];
#pragma unroll
                for (int g = 0; g < G_; g++) {
                    float a = fmaxf(xv - pl[g], 0.0f);
                    float d = fmaxf(ph[g] - xv, 0.0f);
                    float m = a * d;
                    tsh[(cl * G_ + g) * PSTR + pos] = m * m;   // R^2 in weights
                }
            }
        }
        __syncthreads();

        // -- conv, double-buffered over 6 (plane, fi) iterations
        float4 va[2], vb[2];
        float2 vc[2];
        ulonglong2 wv[2][12];

        auto loadIter = [&](int j, int bi) {
            const int p  = q + 8 * (j / 3);          // plane q or q+8
            const int fi = j % 3;
            const float* pb = tsh + p * PSTR + (sy + fi) * TILW + 8 * sxs;
            va[bi] = *reinterpret_cast<const float4*>(pb);
            vb[bi] = *reinterpret_cast<const float4*>(pb + 4);
            vc[bi] = *reinterpret_cast<const float2*>(pb + 8);
            const ulonglong2* wj = reinterpret_cast<const ulonglong2*>(
                wsh + (s * 16 + p) * WCG + fi * 3 * 16);
#pragma unroll
            for (int k = 0; k < 12; k++) wv[bi][k] = wj[k];
        };

        auto computeIter = [&](int bi) {
            u64 e0 = pack2(va[bi].x, va[bi].y);
            u64 e1 = pack2(va[bi].z, va[bi].w);
            u64 e2 = pack2(vb[bi].x, vb[bi].y);
            u64 e3 = pack2(vb[bi].z, vb[bi].w);
            u64 e4 = pack2(vc[bi].x, vc[bi].y);
            u64 o0 = pack2(va[bi].y, va[bi].z);
            u64 o1 = pack2(va[bi].w, vb[bi].x);
            u64 o2 = pack2(vb[bi].y, vb[bi].z);
            u64 o3 = pack2(vb[bi].w, vc[bi].x);
            u64 pj[3][4] = {{e0, e1, e2, e3},    // fj = 0
                            {o0, o1, o2, o3},    // fj = 1
                            {e1, e2, e3, e4}};   // fj = 2
#pragma unroll
            for (int fj = 0; fj < 3; fj++) {
                u64 wd[8] = {wv[bi][fj * 4 + 0].x, wv[bi][fj * 4 + 0].y,
                             wv[bi][fj * 4 + 1].x, wv[bi][fj * 4 + 1].y,
                             wv[bi][fj * 4 + 2].x, wv[bi][fj * 4 + 2].y,
                             wv[bi][fj * 4 + 3].x, wv[bi][fj * 4 + 3].y};
#pragma unroll
                for (int o = 0; o < 8; o++) {
#pragma unroll
                    for (int k = 0; k < 4; k++)
                        acc[o * 4 + k] = fma2(pj[fj][k], wd[o], acc[o * 4 + k]);
                }
            }
        };

        loadIter(0, 0);
#pragma unroll
        for (int j = 0; j < 6; j++) {
            if (j < 5) loadIter(j + 1, (j + 1) & 1);
            computeIter(j & 1);
        }
    }

    // ---- 3-level butterfly half-exchange over the 8 q-groups
#pragma unroll
    for (int lvl = 0; lvl < 3; lvl++) {
        const int mask = 4 << lvl;
        const int half = 16 >> lvl;
        const bool bit = (q >> lvl) & 1;
#pragma unroll
        for (int j = 0; j < 16; j++) {
            if (j < half) {
                u64 lo = acc[j], hi = acc[half + j];
                u64 sent = bit ? lo : hi;
                u64 rec  = __shfl_xor_sync(0xffffffffu, sent, mask);
                acc[j] = add2(bit ? hi : lo, rec);
            }
        }
    }
    // lane q holds acc[0..3] = 4 px-pairs of output channel o = bitrev3(q)
    const int o = ((q & 1) << 2) | (q & 2) | ((q >> 2) & 1);

    const float bo = bsh[o];
    const int oy  = y0 + sy;
    const int ox0 = x0 + 8 * sxs;
    if (oy < HO_) {
        float* op = out + ((b * OUT_ + o) * HO_ + oy) * WO_;
#pragma unroll
        for (int k = 0; k < 4; k++) {
            int ox = ox0 + 2 * k;
            float v0, v1;
            unpack2(acc[k], v0, v1);
            if (ox + 1 < WO_) {
                *reinterpret_cast<float2*>(op + ox) = make_float2(v0 + bo, v1 + bo);
            } else if (ox < WO_) {
                op[ox] = v0 + bo;
            }
        }
    }
}

// ---------------------------------------------------------------------------
extern "C" void kernel_launch(void* const* d_in, const int* in_sizes, int n_in,
                              void* d_out, int out_size) {
    const float* x          = (const float*)d_in[0];
    const float* phase_low  = (const float*)d_in[1];
    const float* phase_high = (const float*)d_in[2];
    const float* weight     = (const float*)d_in[3];
    const float* bias       = (const float*)d_in[4];
    float* out = (float*)d_out;

    dim3 grid(2, 8, B_);                 // 128 blocks x 256 threads, 1 block/SM
    kan_fused_kernel<<<grid, NTHR>>>(x, phase_low, phase_high, weight, bias, out);
}